// round 6
// baseline (speedup 1.0000x reference)
#include <cuda_runtime.h>
#include <cstdint>

#define IN_CH 16
#define OUT_CH 32
#define BATCH 8
#define H 32
#define W 32
#define NCP (IN_CH / 2)            // 8 channel pairs
#define NTAP 9
#define NPAIRTRIP (NCP * NTAP * OUT_CH)   // 2304 float2 per table

typedef unsigned long long ull;

// Packed coefficient tables: [0..2303]=np1, [2304..4607]=sm, [4608..6911]=dsh
// Each entry: float2 (lo = channel 2cp, hi = channel 2cp+1), index (cp*9+tap)*32+o
__device__ float2 g_coef[3 * NPAIRTRIP];
__device__ float  g_base[OUT_CH];

__device__ __forceinline__ ull add2(ull a, ull b) {
    ull r; asm("add.rn.f32x2 %0, %1, %2;" : "=l"(r) : "l"(a), "l"(b)); return r;
}
__device__ __forceinline__ ull fma2(ull a, ull b, ull c) {
    ull r; asm("fma.rn.f32x2 %0, %1, %2, %3;" : "=l"(r) : "l"(a), "l"(b), "l"(c)); return r;
}

// ---------------------------------------------------------------------------
// Kernel 1: coefficients, once.
//   y_i(x) = v1 + sm*d + dsh*|d|, d = x - p1, sm=(s0+s1)/2, dsh=(s1-s0)/2
// ---------------------------------------------------------------------------
__global__ void coef_kernel(const float* __restrict__ pos,
                            const float* __restrict__ val) {
    if (blockIdx.x < 18) {
        int t = blockIdx.x * 256 + threadIdx.x;    // (i, o), i = c*9+tap
        int o = t & 31;
        int i = t >> 5;
        int c = i / 9, tap = i - c * 9;
        int base = t * 3;
        float p0 = pos[base], p1 = pos[base + 1], p2 = pos[base + 2];
        float v0 = val[base], v1 = val[base + 1], v2 = val[base + 2];
        float s0 = (v1 - v0) / (p1 - p0);
        float s1 = (v2 - v1) / (p2 - p1);
        int idx = ((c >> 1) * 9 + tap) * 32 + o;
        int hf = c & 1;
        ((float*)&g_coef[idx])[hf]                 = -p1;
        ((float*)&g_coef[idx + NPAIRTRIP])[hf]     = 0.5f * (s0 + s1);
        ((float*)&g_coef[idx + 2 * NPAIRTRIP])[hf] = 0.5f * (s1 - s0);
    } else if (threadIdx.x < 32) {
        float s = 0.f;
        #pragma unroll 16
        for (int i = 0; i < 144; i++)
            s += val[(i * 32 + threadIdx.x) * 3 + 1];
        g_base[threadIdx.x] = s;
    }
}

// ---------------------------------------------------------------------------
// Kernel 2: main compute. Block = (image, output row), 256 threads = 8 warps.
//   Warp w: pixel group px0 = (w&3)*8 (8 pixels), channel-pair group g = w>>2
//   (cp = 4g..4g+3, i.e. 8 channels). lane = output channel o.
//   8 px/warp halves coef-stream traffic per pixel; 8 independent acc chains.
//   Channel-split halves the per-warp coef stream; two groups are summed
//   through a small padded smem partial.
//   __launch_bounds__(256,3): <=84 regs -> 3 resident blocks = 24 warps/SM.
// ---------------------------------------------------------------------------
#define CH_PAD 18
#define TCOLS 34
#define OFF_COEF 0                                 // 6912 float2 = 55296 B
#define OFF_TILE 55296                             // 3*34*18 floats = 7344 B
#define OFF_PART 62640                             // 2*32*33 floats = 8448 B
#define SMEM_BYTES 71088

__global__ __launch_bounds__(256, 3)
void apc_main(const float* __restrict__ x, float* __restrict__ out) {
    extern __shared__ char sm_raw[];
    ull*   c_np1 = (ull*)(sm_raw + OFF_COEF);
    ull*   c_sm  = c_np1 + NPAIRTRIP;
    ull*   c_dsh = c_np1 + 2 * NPAIRTRIP;
    float* tile  = (float*)(sm_raw + OFF_TILE);
    ull*   tile64 = (ull*)tile;
    float* part  = (float*)(sm_raw + OFF_PART);

    const int tid = threadIdx.x;
    const int b = blockIdx.x >> 5;
    const int y = blockIdx.x & 31;

    // ---- copy packed coef tables global -> smem (float4, coalesced) ----
    {
        const float4* src = (const float4*)g_coef;
        float4* dst = (float4*)c_np1;
        #pragma unroll
        for (int k = 0; k < 14; k++) {
            int idx = tid + k * 256;
            if (idx < 3 * NPAIRTRIP / 2) dst[idx] = src[idx];
        }
    }

    // ---- stage tile rows y-1..y+1, cols -1..32, channel-interleaved ----
    const float* xb = x + b * (IN_CH * H * W);
    for (int idx = tid; idx < 3 * TCOLS * IN_CH; idx += 256) {
        int c   = idx / (3 * TCOLS);          // channel outer: gmem coalesced
        int rem = idx - c * (3 * TCOLS);
        int r   = rem / TCOLS;
        int col = rem - r * TCOLS;
        int gy = y + r - 1;
        int gx = col - 1;
        float v = 0.f;
        if ((unsigned)gy < (unsigned)H && (unsigned)gx < (unsigned)W)
            v = xb[(c * H + gy) * W + gx];
        tile[(r * TCOLS + col) * CH_PAD + c] = v;
    }
    __syncthreads();

    // ---- main loop: 8 px, 4 channel-pairs, 32 o lanes per warp ----
    const int w = tid >> 5;
    const int o = tid & 31;
    const int g   = w >> 2;           // channel-pair group (cp 4g..4g+3)
    const int px0 = (w & 3) << 3;     // 8-pixel group

    ull acc[8] = {0, 0, 0, 0, 0, 0, 0, 0};
    const ull ABS2 = 0x7FFFFFFF7FFFFFFFull;

    #pragma unroll 2
    for (int cc = 0; cc < 4; cc++) {
        const int cp = g * 4 + cc;
        const ull* p1 = c_np1 + cp * (NTAP * 32) + o;
        const ull* p2 = c_sm  + cp * (NTAP * 32) + o;
        const ull* p3 = c_dsh + cp * (NTAP * 32) + o;

        #pragma unroll
        for (int kh = 0; kh < 3; kh++) {
            // one input row of the window: 10 pair-cols, broadcast LDS.64
            ull xr[10];
            #pragma unroll
            for (int m = 0; m < 10; m++)
                xr[m] = tile64[(kh * TCOLS + px0 + m) * (CH_PAD / 2) + cp];

            #pragma unroll
            for (int kw = 0; kw < 3; kw++) {
                const int t = kh * 3 + kw;
                const ull np1 = p1[t * 32];
                const ull smv = p2[t * 32];
                const ull dsh = p3[t * 32];
                #pragma unroll
                for (int p = 0; p < 8; p++) {
                    ull d = add2(xr[p + kw], np1);
                    ull a = d & ABS2;
                    acc[p] = fma2(smv, d, acc[p]);
                    acc[p] = fma2(dsh, a, acc[p]);
                }
            }
        }
    }

    // ---- horizontal reduce -> padded smem partial ----
    #pragma unroll
    for (int p = 0; p < 8; p++) {
        float lo = __uint_as_float((unsigned)acc[p]);
        float hi = __uint_as_float((unsigned)(acc[p] >> 32));
        part[(g * 32 + px0 + p) * 33 + o] = lo + hi;
    }
    __syncthreads();

    // ---- combine groups + base, transposed coalesced store ----
    #pragma unroll
    for (int k = 0; k < 4; k++) {
        int q  = tid + k * 256;
        int oo = q >> 5;
        int px = q & 31;
        float s = part[px * 33 + oo] + part[(32 + px) * 33 + oo] + g_base[oo];
        out[((b * OUT_CH + oo) * H + y) * W + px] = s;
    }
}

extern "C" void kernel_launch(void* const* d_in, const int* in_sizes, int n_in,
                              void* d_out, int out_size) {
    const float* x   = (const float*)d_in[0];
    const float* pos = (const float*)d_in[1];
    const float* val = (const float*)d_in[2];
    float* out = (float*)d_out;

    cudaFuncSetAttribute(apc_main, cudaFuncAttributeMaxDynamicSharedMemorySize,
                         SMEM_BYTES);
    coef_kernel<<<19, 256>>>(pos, val);
    apc_main<<<BATCH * H, 256, SMEM_BYTES>>>(x, out);
}

// round 7
// speedup vs baseline: 1.1236x; 1.1236x over previous
#include <cuda_runtime.h>
#include <cstdint>

#define IN_CH 16
#define OUT_CH 32
#define BATCH 8
#define H 32
#define W 32
#define NCP (IN_CH / 2)            // 8 channel pairs
#define NTAP 9
#define NPAIRTRIP (NCP * NTAP * OUT_CH)   // 2304 float2 per table

typedef unsigned long long ull;

// Packed coefficient tables: [0..2303]=np1, [..]=sm, [..]=dsh
// entry: float2 (lo = ch 2cp, hi = ch 2cp+1), index (cp*9+tap)*32+o
__device__ float2 g_coef[3 * NPAIRTRIP];
__device__ float  g_base[OUT_CH];

__device__ __forceinline__ ull add2(ull a, ull b) {
    ull r; asm("add.rn.f32x2 %0, %1, %2;" : "=l"(r) : "l"(a), "l"(b)); return r;
}
__device__ __forceinline__ ull fma2(ull a, ull b, ull c) {
    ull r; asm("fma.rn.f32x2 %0, %1, %2, %3;" : "=l"(r) : "l"(a), "l"(b), "l"(c)); return r;
}

// ---------------------------------------------------------------------------
// Kernel 1: coefficients, once.
//   y_i(x) = v1 + sm*d + dsh*|d|, d = x - p1, sm=(s0+s1)/2, dsh=(s1-s0)/2
// ---------------------------------------------------------------------------
__global__ void coef_kernel(const float* __restrict__ pos,
                            const float* __restrict__ val) {
    if (blockIdx.x < 18) {
        int t = blockIdx.x * 256 + threadIdx.x;    // (i, o), i = c*9+tap
        int o = t & 31;
        int i = t >> 5;
        int c = i / 9, tap = i - c * 9;
        int base = t * 3;
        float p0 = pos[base], p1 = pos[base + 1], p2 = pos[base + 2];
        float v0 = val[base], v1 = val[base + 1], v2 = val[base + 2];
        float s0 = (v1 - v0) / (p1 - p0);
        float s1 = (v2 - v1) / (p2 - p1);
        int idx = ((c >> 1) * 9 + tap) * 32 + o;
        int hf = c & 1;
        ((float*)&g_coef[idx])[hf]                 = -p1;
        ((float*)&g_coef[idx + NPAIRTRIP])[hf]     = 0.5f * (s0 + s1);
        ((float*)&g_coef[idx + 2 * NPAIRTRIP])[hf] = 0.5f * (s1 - s0);
    } else if (threadIdx.x < 32) {
        float s = 0.f;
        #pragma unroll 16
        for (int i = 0; i < 144; i++)
            s += val[(i * 32 + threadIdx.x) * 3 + 1];
        g_base[threadIdx.x] = s;
    }
}

// ---------------------------------------------------------------------------
// Kernel 2: main compute. ONE full wave: grid 128, block 1024 (32 warps).
//   Block = (image b, row pair y0..y0+1): 64 pixels.
//   Warp w: ch-group g = w>>3 (cp 2g, 2g+1), px-group pg = w&7
//     (row r0 = pg>>2, cols c0 = (pg&3)*8, 8 pixels). lane = o.
//   Coef table staged once per block; tile channel-pair interleaved for
//   native LDS.64; 8 independent f32x2 acc chains per warp.
//   4 ch-groups reduced via padded smem partials.
// ---------------------------------------------------------------------------
#define CH_PAD 18
#define TCOLS 34
#define TROWS 4
#define OFF_COEF 0                                   // 55296 B
#define OFF_TILE 55296                               // 4*34*18*4 = 9792 B
#define OFF_PART 65088                               // 4*64*33*4 = 33792 B
#define SMEM_BYTES 98880

__global__ __launch_bounds__(1024, 1)
void apc_main(const float* __restrict__ x, float* __restrict__ out) {
    extern __shared__ char sm_raw[];
    ull*   c_np1 = (ull*)(sm_raw + OFF_COEF);
    ull*   c_sm  = c_np1 + NPAIRTRIP;
    ull*   c_dsh = c_np1 + 2 * NPAIRTRIP;
    float* tile  = (float*)(sm_raw + OFF_TILE);
    ull*   tile64 = (ull*)tile;
    float* part  = (float*)(sm_raw + OFF_PART);

    const int tid = threadIdx.x;
    const int b  = blockIdx.x >> 4;          // image
    const int y0 = (blockIdx.x & 15) << 1;   // first output row

    // ---- coef tables global -> smem, once per block (float4, coalesced) ----
    {
        const float4* src = (const float4*)g_coef;
        float4* dst = (float4*)c_np1;
        #pragma unroll
        for (int k = 0; k < 4; k++) {
            int idx = tid + k * 1024;
            if (idx < 3 * NPAIRTRIP / 2) dst[idx] = src[idx];
        }
    }

    // ---- stage tile rows y0-1..y0+2, cols -1..32, channel-interleaved ----
    const float* xb = x + b * (IN_CH * H * W);
    for (int idx = tid; idx < TROWS * TCOLS * IN_CH; idx += 1024) {
        int c   = idx / (TROWS * TCOLS);      // channel outer: gmem coalesced
        int rem = idx - c * (TROWS * TCOLS);
        int r   = rem / TCOLS;
        int col = rem - r * TCOLS;
        int gy = y0 + r - 1;
        int gx = col - 1;
        float v = 0.f;
        if ((unsigned)gy < (unsigned)H && (unsigned)gx < (unsigned)W)
            v = xb[(c * H + gy) * W + gx];
        tile[(r * TCOLS + col) * CH_PAD + c] = v;
    }
    __syncthreads();

    // ---- main loop: 8 px, 2 channel-pairs, 32 o lanes per warp ----
    const int w  = tid >> 5;
    const int o  = tid & 31;
    const int g  = w >> 3;                 // ch-group: cp = 2g, 2g+1
    const int pg = w & 7;
    const int r0 = pg >> 2;                // output row within pair
    const int c0 = (pg & 3) << 3;          // 8-pixel column group

    ull acc[8] = {0, 0, 0, 0, 0, 0, 0, 0};
    const ull ABS2 = 0x7FFFFFFF7FFFFFFFull;

    #pragma unroll
    for (int cc = 0; cc < 2; cc++) {
        const int cp = g * 2 + cc;
        const ull* p1 = c_np1 + cp * (NTAP * 32) + o;
        const ull* p2 = c_sm  + cp * (NTAP * 32) + o;
        const ull* p3 = c_dsh + cp * (NTAP * 32) + o;

        #pragma unroll
        for (int kh = 0; kh < 3; kh++) {
            // one window row: 10 pair-cols, warp-uniform broadcast LDS.64
            ull xr[10];
            #pragma unroll
            for (int m = 0; m < 10; m++)
                xr[m] = tile64[((r0 + kh) * TCOLS + c0 + m) * (CH_PAD / 2) + cp];

            #pragma unroll
            for (int kw = 0; kw < 3; kw++) {
                const int t = kh * 3 + kw;
                const ull np1 = p1[t * 32];
                const ull smv = p2[t * 32];
                const ull dsh = p3[t * 32];
                #pragma unroll
                for (int p = 0; p < 8; p++) {
                    ull d = add2(xr[p + kw], np1);
                    ull a = d & ABS2;
                    acc[p] = fma2(smv, d, acc[p]);
                    acc[p] = fma2(dsh, a, acc[p]);
                }
            }
        }
    }

    // ---- horizontal pair reduce -> padded smem partial ----
    #pragma unroll
    for (int p = 0; p < 8; p++) {
        float lo = __uint_as_float((unsigned)acc[p]);
        float hi = __uint_as_float((unsigned)(acc[p] >> 32));
        int px = (r0 << 5) + c0 + p;               // 0..63 within row pair
        part[(g * 64 + px) * 33 + o] = lo + hi;    // lanes contiguous: clean
    }
    __syncthreads();

    // ---- combine 4 ch-groups + base, transposed coalesced store ----
    #pragma unroll
    for (int k = 0; k < 2; k++) {
        int q  = tid + k * 1024;       // 0..2047 -> (o, px64)
        int oo = q >> 6;
        int px = q & 63;
        float s = g_base[oo];
        #pragma unroll
        for (int gg = 0; gg < 4; gg++)
            s += part[(gg * 64 + px) * 33 + oo];   // stride-33: conflict-free
        int r = px >> 5, col = px & 31;
        out[((b * OUT_CH + oo) * H + (y0 + r)) * W + col] = s;
    }
}

extern "C" void kernel_launch(void* const* d_in, const int* in_sizes, int n_in,
                              void* d_out, int out_size) {
    const float* x   = (const float*)d_in[0];
    const float* pos = (const float*)d_in[1];
    const float* val = (const float*)d_in[2];
    float* out = (float*)d_out;

    cudaFuncSetAttribute(apc_main, cudaFuncAttributeMaxDynamicSharedMemorySize,
                         SMEM_BYTES);
    coef_kernel<<<19, 256>>>(pos, val);
    apc_main<<<BATCH * (H / 2), 1024, SMEM_BYTES>>>(x, out);
}

// round 8
// speedup vs baseline: 1.1696x; 1.0409x over previous
#include <cuda_runtime.h>
#include <cstdint>

#define IN_CH 16
#define OUT_CH 32
#define BATCH 8
#define H 32
#define W 32
#define NCP (IN_CH / 2)            // 8 channel pairs
#define NTAP 9
#define NPAIRTRIP (NCP * NTAP * OUT_CH)   // 2304 float2 per table

typedef unsigned long long ull;

// Packed coefficient tables, entry float2 (lo = ch 2cp, hi = ch 2cp+1),
// index (cp*9+tap)*32 + o
__device__ float2 g_np1[NPAIRTRIP];
__device__ float2 g_sm [NPAIRTRIP];
__device__ float2 g_dsh[NPAIRTRIP];
__device__ float  g_base[OUT_CH];

__device__ __forceinline__ ull add2(ull a, ull b) {
    ull r; asm("add.rn.f32x2 %0, %1, %2;" : "=l"(r) : "l"(a), "l"(b)); return r;
}
__device__ __forceinline__ ull fma2(ull a, ull b, ull c) {
    ull r; asm("fma.rn.f32x2 %0, %1, %2, %3;" : "=l"(r) : "l"(a), "l"(b), "l"(c)); return r;
}

// ---------------------------------------------------------------------------
// Kernel 1: coefficients, once.
//   y_i(x) = v1 + sm*d + dsh*|d|, d = x - p1, sm=(s0+s1)/2, dsh=(s1-s0)/2
// ---------------------------------------------------------------------------
__global__ void coef_kernel(const float* __restrict__ pos,
                            const float* __restrict__ val) {
    if (blockIdx.x < 18) {
        int t = blockIdx.x * 256 + threadIdx.x;    // (i, o), i = c*9+tap
        int o = t & 31;
        int i = t >> 5;
        int c = i / 9, tap = i - c * 9;
        int base = t * 3;
        float p0 = pos[base], p1 = pos[base + 1], p2 = pos[base + 2];
        float v0 = val[base], v1 = val[base + 1], v2 = val[base + 2];
        float s0 = (v1 - v0) / (p1 - p0);
        float s1 = (v2 - v1) / (p2 - p1);
        int idx = ((c >> 1) * 9 + tap) * 32 + o;
        int hf = c & 1;
        ((float*)&g_np1[idx])[hf] = -p1;
        ((float*)&g_sm [idx])[hf] = 0.5f * (s0 + s1);
        ((float*)&g_dsh[idx])[hf] = 0.5f * (s1 - s0);
    } else if (threadIdx.x < 32) {
        float s = 0.f;
        #pragma unroll 16
        for (int i = 0; i < 144; i++)
            s += val[(i * 32 + threadIdx.x) * 3 + 1];
        g_base[threadIdx.x] = s;
    }
}

// ---------------------------------------------------------------------------
// Kernel 2: main compute. Grid 1024, block 256 (8 warps).
//   Block = (image b, row y, col-group cg): 8 output pixels.
//   Warp w = channel-pair cp; lane = output channel o.
//   sm/dsh coef pairs in REGISTERS (loaded once, coalesced LDG.64);
//   np1 one LDG.64 per tap (L2-resident, amortized over 8 px).
//   Main loop has NO per-lane LDS: only 30 broadcast LDS.64 x-loads.
//   8 cp-partials reduced through a tiny smem array.
// ---------------------------------------------------------------------------
#define TC 10                         // 8 px + 2 halo cols
#define TILE_FLOATS (3 * TC * IN_CH)  // 480
// smem: tile 480 floats (1920 B) + part[8cp][8px][33] floats (8448 B)
#define OFF_TILE 0
#define OFF_PART 1920
#define SMEM_BYTES (1920 + 8448)

__global__ __launch_bounds__(256, 3)
void apc_main(const float* __restrict__ x, float* __restrict__ out) {
    __shared__ float sm_tile[TILE_FLOATS];
    __shared__ float sm_part[NCP * 8 * 33];
    ull* tile64 = (ull*)sm_tile;

    const int tid = threadIdx.x;
    const int blk = blockIdx.x;
    const int b  = blk >> 7;             // image
    const int y  = (blk >> 2) & 31;      // output row
    const int c0 = (blk & 3) << 3;       // first of 8 output cols

    // ---- stage tile rows y-1..y+1, cols c0-1..c0+8, ch-interleaved ----
    const float* xb = x + b * (IN_CH * H * W);
    for (int idx = tid; idx < TILE_FLOATS; idx += 256) {
        int c   = idx / (3 * TC);
        int rem = idx - c * (3 * TC);
        int r   = rem / TC;
        int col = rem - r * TC;
        int gy = y + r - 1;
        int gx = c0 + col - 1;
        float v = 0.f;
        if ((unsigned)gy < (unsigned)H && (unsigned)gx < (unsigned)W)
            v = xb[(c * H + gy) * W + gx];
        sm_tile[(r * TC + col) * IN_CH + c] = v;
    }

    // ---- coef pairs into registers (coalesced LDG.64, once per warp) ----
    const int cp = tid >> 5;          // warp = channel pair
    const int o  = tid & 31;          // lane = output channel
    const ull* gsm  = (const ull*)g_sm  + cp * (NTAP * 32) + o;
    const ull* gdsh = (const ull*)g_dsh + cp * (NTAP * 32) + o;
    const ull* gnp  = (const ull*)g_np1 + cp * (NTAP * 32) + o;
    ull csm[NTAP], cdsh[NTAP];
    #pragma unroll
    for (int t = 0; t < NTAP; t++) {
        csm[t]  = gsm [t * 32];
        cdsh[t] = gdsh[t * 32];
    }
    __syncthreads();

    // ---- main loop: 8 px, 9 taps, zero per-lane LDS ----
    ull acc[8] = {0, 0, 0, 0, 0, 0, 0, 0};
    const ull ABS2 = 0x7FFFFFFF7FFFFFFFull;

    #pragma unroll
    for (int kh = 0; kh < 3; kh++) {
        // one window row: 10 pair-values, warp-uniform broadcast LDS.64
        ull xr[TC];
        #pragma unroll
        for (int m = 0; m < TC; m++)
            xr[m] = tile64[(kh * TC + m) * NCP + cp];

        #pragma unroll
        for (int kw = 0; kw < 3; kw++) {
            const int t = kh * 3 + kw;
            const ull np1 = gnp[t * 32];     // LDG.64, L2-hot, reused x8
            const ull smv = csm[t];
            const ull dsh = cdsh[t];
            #pragma unroll
            for (int p = 0; p < 8; p++) {
                ull d = add2(xr[p + kw], np1);
                ull a = d & ABS2;
                acc[p] = fma2(smv, d, acc[p]);
                acc[p] = fma2(dsh, a, acc[p]);
            }
        }
    }

    // ---- horizontal pair reduce -> padded smem partials ----
    #pragma unroll
    for (int p = 0; p < 8; p++) {
        float lo = __uint_as_float((unsigned)acc[p]);
        float hi = __uint_as_float((unsigned)(acc[p] >> 32));
        sm_part[(cp * 8 + p) * 33 + o] = lo + hi;   // lanes contiguous
    }
    __syncthreads();

    // ---- combine 8 cp-partials + base; coalesced store (px in lane) ----
    {
        const int px = tid & 7;
        const int oo = tid >> 3;
        float s = g_base[oo];
        #pragma unroll
        for (int g = 0; g < NCP; g++)
            s += sm_part[(g * 8 + px) * 33 + oo];
        out[((b * OUT_CH + oo) * H + y) * W + c0 + px] = s;
    }
}

extern "C" void kernel_launch(void* const* d_in, const int* in_sizes, int n_in,
                              void* d_out, int out_size) {
    const float* x   = (const float*)d_in[0];
    const float* pos = (const float*)d_in[1];
    const float* val = (const float*)d_in[2];
    float* out = (float*)d_out;

    coef_kernel<<<19, 256>>>(pos, val);
    apc_main<<<1024, 256>>>(x, out);
}

// round 9
// speedup vs baseline: 1.2712x; 1.0869x over previous
#include <cuda_runtime.h>
#include <cstdint>

#define IN_CH 16
#define OUT_CH 32
#define BATCH 8
#define H 32
#define W 32
#define NCP (IN_CH / 2)            // 8 channel pairs
#define NTAP 9

typedef unsigned long long ull;

__device__ __forceinline__ ull add2(ull a, ull b) {
    ull r; asm("add.rn.f32x2 %0, %1, %2;" : "=l"(r) : "l"(a), "l"(b)); return r;
}
__device__ __forceinline__ ull fma2(ull a, ull b, ull c) {
    ull r; asm("fma.rn.f32x2 %0, %1, %2, %3;" : "=l"(r) : "l"(a), "l"(b), "l"(c)); return r;
}
__device__ __forceinline__ ull pack2(float lo, float hi) {
    ull r;
    asm("mov.b64 %0, {%1, %2};" : "=l"(r)
        : "r"(__float_as_uint(lo)), "r"(__float_as_uint(hi)));
    return r;
}

// ---------------------------------------------------------------------------
// Single fused kernel. Grid 256 = (image, output row), 256 threads = 8 warps.
//   Warp = channel pair cp (ch 2cp, 2cp+1); lane = output channel o.
//   Prologue (once per block):
//     - stage 3x34x16 input tile, channel-pair interleaved (zero halo)
//     - compute piecewise coefs y=v1+sm*d+dsh*|d| for this lane's 18 (i,o)
//       pairs directly into REGISTERS (np1/sm/dsh, 27 ull)
//     - per-warp sum of v1 -> vpart (base term), reduced in epilogue
//   Main: 4 col-groups x 8 px, all-register coefs, only broadcast LDS.
//   Epilogue: 8 cp-partials + base summed, transposed coalesced store.
// ---------------------------------------------------------------------------
#define TCOLS 34
#define TILE_PAIRS (3 * TCOLS * NCP)     // 816 ull

__global__ __launch_bounds__(256, 2)
void apc_fused(const float* __restrict__ x, const float* __restrict__ pos,
               const float* __restrict__ val, float* __restrict__ out) {
    __shared__ ull  sm_tile64[TILE_PAIRS];           // 6528 B
    __shared__ float sm_part[NCP * 32 * 33];         // 33792 B
    __shared__ float sm_vpart[NCP * 32];             // 1024 B
    float* sm_tile = (float*)sm_tile64;

    const int tid = threadIdx.x;
    const int b = blockIdx.x >> 5;       // image
    const int y = blockIdx.x & 31;       // output row
    const int cp = tid >> 5;             // warp = channel pair
    const int o  = tid & 31;             // lane = output channel

    // ---- stage tile rows y-1..y+1, cols -1..32, ch-interleaved ----
    const float* xb = x + b * (IN_CH * H * W);
    for (int idx = tid; idx < 3 * TCOLS * IN_CH; idx += 256) {
        int c   = idx / (3 * TCOLS);          // channel outer: coalesced LDG
        int rem = idx - c * (3 * TCOLS);
        int r   = rem / TCOLS;
        int col = rem - r * TCOLS;
        int gy = y + r - 1;
        int gx = col - 1;
        float v = 0.f;
        if ((unsigned)gy < (unsigned)H && (unsigned)gx < (unsigned)W)
            v = xb[(c * H + gy) * W + gx];
        sm_tile[(r * TCOLS + col) * IN_CH + c] = v;
    }

    // ---- coefficients for this lane's 18 (i, o) pairs, into registers ----
    //   y_i(x) = v1 + sm*d + dsh*|d|, d = x - p1
    //   sm = (s0+s1)/2, dsh = (s1-s0)/2, s0=(v1-v0)/(p1-p0), s1=(v2-v1)/(p2-p1)
    ull cnp[NTAP], csm[NTAP], cdsh[NTAP];
    {
        float vs = 0.f;
        #pragma unroll
        for (int t = 0; t < NTAP; t++) {
            float npf[2], smf[2], dsf[2];
            #pragma unroll
            for (int hf = 0; hf < 2; hf++) {
                int i = (2 * cp + hf) * NTAP + t;
                int base = (i * 32 + o) * 3;
                float p0 = pos[base], p1 = pos[base + 1], p2 = pos[base + 2];
                float v0 = val[base], v1 = val[base + 1], v2 = val[base + 2];
                float s0 = __fdividef(v1 - v0, p1 - p0);
                float s1 = __fdividef(v2 - v1, p2 - p1);
                npf[hf] = -p1;
                smf[hf] = 0.5f * (s0 + s1);
                dsf[hf] = 0.5f * (s1 - s0);
                vs += v1;
            }
            cnp[t]  = pack2(npf[0], npf[1]);
            csm[t]  = pack2(smf[0], smf[1]);
            cdsh[t] = pack2(dsf[0], dsf[1]);
        }
        sm_vpart[cp * 32 + o] = vs;      // per-warp v1 partial (base term)
    }
    __syncthreads();

    // ---- main: 4 col-groups of 8 px, 9 taps, all-register coefficients ----
    const ull ABS2 = 0x7FFFFFFF7FFFFFFFull;
    #pragma unroll
    for (int cg = 0; cg < 4; cg++) {
        const int c0 = cg << 3;
        ull acc[8] = {0, 0, 0, 0, 0, 0, 0, 0};

        #pragma unroll
        for (int kh = 0; kh < 3; kh++) {
            // one window row: 10 pair-values, warp-uniform broadcast LDS.64
            ull xr[10];
            #pragma unroll
            for (int m = 0; m < 10; m++)
                xr[m] = sm_tile64[(kh * TCOLS + c0 + m) * NCP + cp];

            #pragma unroll
            for (int kw = 0; kw < 3; kw++) {
                const int t = kh * 3 + kw;
                const ull np1 = cnp[t];
                const ull smv = csm[t];
                const ull dsh = cdsh[t];
                #pragma unroll
                for (int p = 0; p < 8; p++) {
                    ull d = add2(xr[p + kw], np1);
                    ull a = d & ABS2;
                    acc[p] = fma2(smv, d, acc[p]);
                    acc[p] = fma2(dsh, a, acc[p]);
                }
            }
        }

        // horizontal pair reduce -> padded smem partials (lanes contiguous)
        #pragma unroll
        for (int p = 0; p < 8; p++) {
            float lo = __uint_as_float((unsigned)acc[p]);
            float hi = __uint_as_float((unsigned)(acc[p] >> 32));
            sm_part[(cp * 32 + c0 + p) * 33 + o] = lo + hi;
        }
    }
    __syncthreads();

    // ---- combine 8 cp-partials + base; transposed coalesced store ----
    #pragma unroll
    for (int k = 0; k < 4; k++) {
        int q  = tid + k * 256;        // (oo = q>>5 warp-uniform, px = lane)
        int oo = q >> 5;
        int px = q & 31;
        float s = 0.f;
        #pragma unroll
        for (int g = 0; g < NCP; g++)
            s += sm_vpart[g * 32 + oo];            // broadcast
        #pragma unroll
        for (int g = 0; g < NCP; g++)
            s += sm_part[(g * 32 + px) * 33 + oo]; // stride-33: conflict-free
        out[((b * OUT_CH + oo) * H + y) * W + px] = s;
    }
}

extern "C" void kernel_launch(void* const* d_in, const int* in_sizes, int n_in,
                              void* d_out, int out_size) {
    const float* x   = (const float*)d_in[0];
    const float* pos = (const float*)d_in[1];
    const float* val = (const float*)d_in[2];
    float* out = (float*)d_out;

    apc_fused<<<BATCH * H, 256>>>(x, pos, val, out);
}

// round 10
// speedup vs baseline: 1.2959x; 1.0194x over previous
#include <cuda_runtime.h>
#include <cstdint>

#define IN_CH 16
#define OUT_CH 32
#define BATCH 8
#define H 32
#define W 32
#define NCP (IN_CH / 2)            // 8 channel pairs
#define NTAP 9

typedef unsigned long long ull;

__device__ __forceinline__ ull add2(ull a, ull b) {
    ull r; asm("add.rn.f32x2 %0, %1, %2;" : "=l"(r) : "l"(a), "l"(b)); return r;
}
__device__ __forceinline__ ull fma2(ull a, ull b, ull c) {
    ull r; asm("fma.rn.f32x2 %0, %1, %2, %3;" : "=l"(r) : "l"(a), "l"(b), "l"(c)); return r;
}
__device__ __forceinline__ ull pack2(float lo, float hi) {
    ull r;
    asm("mov.b64 %0, {%1, %2};" : "=l"(r)
        : "r"(__float_as_uint(lo)), "r"(__float_as_uint(hi)));
    return r;
}

// ---------------------------------------------------------------------------
// Single fused kernel, ONE WAVE.
//   Grid 128 = (image b, row pair y0..y0+1). Block 512 = 16 warps.
//   Warp w: cp = w&7 (channels 2cp,2cp+1), r0 = w>>3 (row of pair). lane = o.
//   Prologue: stage 4x34x16 tile (ch-interleaved, zero halo) + compute
//     piecewise coefs y=v1+sm*d+dsh*|d| into REGISTERS (27 ull / thread,
//     duplicated across the 2 row-warps per cp — parallel, free in latency).
//   Main: 4 col-groups x 8 px, all-register coefs, only broadcast LDS.64.
//   Epilogue: 8 cp-partials + v1-base summed via padded smem, transposed
//     coalesced store.
// ---------------------------------------------------------------------------
#define TCOLS 34
#define TROWS 4
#define TILE_PAIRS (TROWS * TCOLS * NCP)     // 1088 ull = 8704 B

#define OFF_TILE  0
#define OFF_PART  8704                        // 8*64*33*4 = 67584 B
#define OFF_VPART 76288                       // 8*32*4 = 1024 B
#define SMEM_BYTES 77312

__global__ void apc_fused(const float* __restrict__ x,
                          const float* __restrict__ pos,
                          const float* __restrict__ val,
                          float* __restrict__ out) {
    extern __shared__ char sm_raw[];
    ull*   sm_tile64 = (ull*)(sm_raw + OFF_TILE);
    float* sm_tile   = (float*)sm_tile64;
    float* sm_part   = (float*)(sm_raw + OFF_PART);
    float* sm_vpart  = (float*)(sm_raw + OFF_VPART);

    const int tid = threadIdx.x;
    const int b  = blockIdx.x >> 4;           // image
    const int y0 = (blockIdx.x & 15) << 1;    // first output row of pair
    const int w  = tid >> 5;
    const int o  = tid & 31;                  // lane = output channel
    const int cp = w & 7;                     // channel pair
    const int r0 = w >> 3;                    // row within pair (0/1)

    // ---- stage tile rows y0-1..y0+2, cols -1..32, ch-interleaved ----
    const float* xb = x + b * (IN_CH * H * W);
    for (int idx = tid; idx < TROWS * TCOLS * IN_CH; idx += 512) {
        int c   = idx / (TROWS * TCOLS);      // channel outer: coalesced LDG
        int rem = idx - c * (TROWS * TCOLS);
        int r   = rem / TCOLS;
        int col = rem - r * TCOLS;
        int gy = y0 + r - 1;
        int gx = col - 1;
        float v = 0.f;
        if ((unsigned)gy < (unsigned)H && (unsigned)gx < (unsigned)W)
            v = xb[(c * H + gy) * W + gx];
        sm_tile[(r * TCOLS + col) * IN_CH + c] = v;
    }

    // ---- coefficients for this lane's 18 (i, o) pairs -> registers ----
    //   y_i(x) = v1 + sm*d + dsh*|d|, d = x - p1
    ull cnp[NTAP], csm[NTAP], cdsh[NTAP];
    {
        float vs = 0.f;
        #pragma unroll
        for (int t = 0; t < NTAP; t++) {
            float npf[2], smf[2], dsf[2];
            #pragma unroll
            for (int hf = 0; hf < 2; hf++) {
                int i = (2 * cp + hf) * NTAP + t;
                int base = (i * 32 + o) * 3;
                float p0 = pos[base], p1 = pos[base + 1], p2 = pos[base + 2];
                float v0 = val[base], v1 = val[base + 1], v2 = val[base + 2];
                float s0 = __fdividef(v1 - v0, p1 - p0);
                float s1 = __fdividef(v2 - v1, p2 - p1);
                npf[hf] = -p1;
                smf[hf] = 0.5f * (s0 + s1);
                dsf[hf] = 0.5f * (s1 - s0);
                vs += v1;
            }
            cnp[t]  = pack2(npf[0], npf[1]);
            csm[t]  = pack2(smf[0], smf[1]);
            cdsh[t] = pack2(dsf[0], dsf[1]);
        }
        if (r0 == 0) sm_vpart[cp * 32 + o] = vs;   // base term, once per cp
    }
    __syncthreads();

    // ---- main: 4 col-groups of 8 px, 9 taps, all-register coefficients ----
    const ull ABS2 = 0x7FFFFFFF7FFFFFFFull;
    #pragma unroll
    for (int cg = 0; cg < 4; cg++) {
        const int c0 = cg << 3;
        ull acc[8] = {0, 0, 0, 0, 0, 0, 0, 0};

        #pragma unroll
        for (int kh = 0; kh < 3; kh++) {
            // window row r0+kh: 10 pair-values, warp-uniform broadcast LDS.64
            ull xr[10];
            #pragma unroll
            for (int m = 0; m < 10; m++)
                xr[m] = sm_tile64[((r0 + kh) * TCOLS + c0 + m) * NCP + cp];

            #pragma unroll
            for (int kw = 0; kw < 3; kw++) {
                const int t = kh * 3 + kw;
                const ull np1 = cnp[t];
                const ull smv = csm[t];
                const ull dsh = cdsh[t];
                #pragma unroll
                for (int p = 0; p < 8; p++) {
                    ull d = add2(xr[p + kw], np1);
                    ull a = d & ABS2;
                    acc[p] = fma2(smv, d, acc[p]);
                    acc[p] = fma2(dsh, a, acc[p]);
                }
            }
        }

        // horizontal pair reduce -> padded smem partials (lanes contiguous)
        #pragma unroll
        for (int p = 0; p < 8; p++) {
            float lo = __uint_as_float((unsigned)acc[p]);
            float hi = __uint_as_float((unsigned)(acc[p] >> 32));
            sm_part[(cp * 64 + (r0 << 5) + c0 + p) * 33 + o] = lo + hi;
        }
    }
    __syncthreads();

    // ---- combine 8 cp-partials + base; transposed coalesced store ----
    #pragma unroll
    for (int k = 0; k < 4; k++) {
        int q  = tid + k * 512;       // 0..2047: (oo = q>>6, px64 = q&63)
        int oo = q >> 6;
        int px = q & 63;
        float s = 0.f;
        #pragma unroll
        for (int g = 0; g < NCP; g++)
            s += sm_vpart[g * 32 + oo];             // warp-uniform broadcast
        #pragma unroll
        for (int g = 0; g < NCP; g++)
            s += sm_part[(g * 64 + px) * 33 + oo];  // stride-33: conflict-free
        int r = px >> 5, col = px & 31;
        out[((b * OUT_CH + oo) * H + (y0 + r)) * W + col] = s;
    }
}

extern "C" void kernel_launch(void* const* d_in, const int* in_sizes, int n_in,
                              void* d_out, int out_size) {
    const float* x   = (const float*)d_in[0];
    const float* pos = (const float*)d_in[1];
    const float* val = (const float*)d_in[2];
    float* out = (float*)d_out;

    cudaFuncSetAttribute(apc_fused, cudaFuncAttributeMaxDynamicSharedMemorySize,
                         SMEM_BYTES);
    apc_fused<<<BATCH * (H / 2), 512, SMEM_BYTES>>>(x, pos, val, out);
}